// round 10
// baseline (speedup 1.0000x reference)
#include <cuda_runtime.h>
#include <math.h>
#include <stdint.h>

#define BB 2
#define NNPTS 4096
#define CF 64
#define KNN 32
#define NTOT (BB*NNPTS)

// ---------------- scratch (static __device__, no allocs) ----------------
__device__ float  g_K[(size_t)BB*NNPTS*NNPTS];   // 128 MB transport kernel
__device__ float  g_f0n[NTOT*CF];
__device__ float  g_f1n[NTOT*CF];
__device__ float  g_n0[NTOT];
__device__ float  g_n1[NTOT];
__device__ float4 g_pts0[NTOT];                  // packed (x,y,z,|p|^2) of pc0
__device__ float  g_colsum[NTOT];
__device__ float4 g_w4t[NTOT];                   // transposed (b, b*x, b*y, b*z)
__device__ float  g_otflow[NTOT*3];
__device__ int    g_idx[NTOT*KNN];
__device__ float  g_y2[NTOT*64];                 // x1 @ W2a (pre-gather transform)
__device__ float  g_y3[NTOT*128];                // x2 @ W3a
// transposed weights (Wt[c][k]) for contiguous per-thread float4 reads
__device__ float  g_t_w12[32*32],  g_t_w13[32*32];
__device__ float  g_t_w22[64*64],  g_t_w23[64*64];
__device__ float  g_t_w32[128*128],g_t_w33[128*128];
__device__ float  g_t_w2a[64*32];                // (w2_1 rows 0..31)^T
__device__ float  g_t_w3a[128*64];               // (w3_1 rows 0..63)^T

__device__ __forceinline__ float lrelu(float x){ return (x > 0.f) ? x : 0.1f*x; }

// ---------------- prep part 1: point norms + packed pts + colsum zero ----
__global__ __launch_bounds__(256)
void prep_norm_kernel(const float* __restrict__ pc0, const float* __restrict__ pc1)
{
    int i = blockIdx.x*blockDim.x + threadIdx.x;
    if (i >= 2*NTOT) return;
    int which = i / NTOT, row = i % NTOT;
    const float* pc = which ? pc1 : pc0;
    float x = pc[row*3+0], y = pc[row*3+1], z = pc[row*3+2];
    float n2 = x*x + y*y + z*z;
    if (which) g_n1[row] = n2;
    else {
        g_n0[row] = n2; g_colsum[row] = 0.f;
        g_pts0[row] = make_float4(x, y, z, n2);
    }
}

// ---------------- prep part 2: feature normalize -------------------------
__global__ __launch_bounds__(256)
void prep_feat_kernel(const float* __restrict__ f0, const float* __restrict__ f1)
{
    int w    = (blockIdx.x*blockDim.x + threadIdx.x) >> 5;
    int lane = threadIdx.x & 31;
    if (w >= 2*NTOT) return;
    int which = w / NTOT;
    int row   = w % NTOT;
    const float* f = which ? f1 : f0;
    float v0 = f[row*CF + lane];
    float v1 = f[row*CF + 32 + lane];
    float ss = v0*v0 + v1*v1;
    #pragma unroll
    for (int o = 16; o > 0; o >>= 1) ss += __shfl_xor_sync(0xffffffffu, ss, o);
    float inv = rsqrtf(ss + 1e-8f);
    float* out = which ? g_f1n : g_f0n;
    out[row*CF + lane]      = v0*inv;
    out[row*CF + 32 + lane] = v1*inv;
}

// ---------------- weight transpose (tiny) --------------------------------
__global__ __launch_bounds__(256)
void wtrans_kernel(const float* __restrict__ w1_2, const float* __restrict__ w1_3,
                   const float* __restrict__ w2_2, const float* __restrict__ w2_3,
                   const float* __restrict__ w3_2, const float* __restrict__ w3_3,
                   const float* __restrict__ w2_1, const float* __restrict__ w3_1)
{
    int i = blockIdx.x*256 + threadIdx.x;
    if (i < 1024) {
        int k = i/32, c = i%32;
        g_t_w12[c*32+k] = w1_2[i]; g_t_w13[c*32+k] = w1_3[i];
    } else if (i < 5120) {
        int j = i-1024; int k = j/64, c = j%64;
        g_t_w22[c*64+k] = w2_2[j]; g_t_w23[c*64+k] = w2_3[j];
    } else if (i < 21504) {
        int j = i-5120; int k = j/128, c = j%128;
        g_t_w32[c*128+k] = w3_2[j]; g_t_w33[c*128+k] = w3_3[j];
    } else if (i < 23552) {
        int j = i-21504; int k = j/64, c = j%64;       // w2_1 rows 0..31
        g_t_w2a[c*32+k] = w2_1[j];
    } else if (i < 31744) {
        int j = i-23552; int k = j/128, c = j%128;     // w3_1 rows 0..63
        g_t_w3a[c*64+k] = w3_1[j];
    }
}

// ---------------- KNN: radix-select 32 smallest sqdists per row ----------
__global__ __launch_bounds__(256)
void knn_kernel()
{
    int n = blockIdx.x; int b = n / NNPTS;
    const float4* pts = g_pts0 + b*NNPTS;
    int tid = threadIdx.x;
    int lane = tid & 31;
    float4 q = g_pts0[n];
    unsigned key[16];
    #pragma unroll
    for (int i = 0; i < 16; i++) {
        float4 p = pts[tid + i*256];
        float dot = fmaf(p.x, q.x, fmaf(p.y, q.y, p.z*q.z));
        float d = q.w + p.w - 2.0f*dot;
        unsigned u = __float_as_uint(d);
        u = (u & 0x80000000u) ? ~u : (u | 0x80000000u);
        key[i] = u;
    }
    __shared__ int hist[256];
    __shared__ unsigned s_prefix;
    __shared__ int s_krem, s_cl, s_ct;
    __shared__ int s_out[KNN];
    __shared__ int s_tie[64];
    if (tid == 0) { s_prefix = 0u; s_krem = KNN; s_cl = 0; s_ct = 0; }
    for (int r = 0; r < 4; r++) {
        int shift = 24 - 8*r;
        hist[tid] = 0;
        __syncthreads();
        unsigned pref = s_prefix;
        unsigned msk  = (r == 0) ? 0u : (0xFFFFFFFFu << (32 - 8*r));
        #pragma unroll
        for (int i = 0; i < 16; i++)
            if ((key[i] & msk) == (pref & msk))
                atomicAdd(&hist[(key[i] >> shift) & 255], 1);
        __syncthreads();
        if (tid < 32) {                    // warp-0 parallel scan of 256 bins
            int krem = s_krem;
            int loc[8]; int tot = 0;
            #pragma unroll
            for (int j = 0; j < 8; j++) { loc[j] = hist[tid*8 + j]; tot += loc[j]; }
            int incl = tot;
            #pragma unroll
            for (int o = 1; o < 32; o <<= 1) {
                int x = __shfl_up_sync(0xffffffffu, incl, o);
                if (lane >= o) incl += x;
            }
            int excl = incl - tot;
            if (excl < krem && krem <= incl) {
                int rem = krem - excl;
                int d = 0;
                #pragma unroll
                for (int j = 0; j < 7; j++) if (rem > loc[d]) { rem -= loc[d]; d++; }
                s_prefix = pref | ((unsigned)(tid*8 + d) << shift);
                s_krem = rem;
            }
        }
        __syncthreads();
    }
    unsigned pivot = s_prefix;
    #pragma unroll
    for (int i = 0; i < 16; i++) {
        unsigned u = key[i];
        if (u < pivot)       { int p = atomicAdd(&s_cl, 1); s_out[p] = tid + i*256; }
        else if (u == pivot) { int t = atomicAdd(&s_ct, 1); if (t < 64) s_tie[t] = tid + i*256; }
    }
    __syncthreads();
    if (tid == 0) {
        int cl = s_cl;
        int nt = (s_ct < 64) ? s_ct : 64;
        int need = KNN - cl;                 // ties filled by lowest index (jax tie-break)
        for (int s = 0; s < need; s++) {
            int best = 0x7FFFFFFF, bi = 0;
            for (int t = 0; t < nt; t++) if (s_tie[t] < best) { best = s_tie[t]; bi = t; }
            s_tie[bi] = 0x7FFFFFFF;
            s_out[cl + s] = best;
        }
    }
    __syncthreads();
    if (tid < KNN) g_idx[n*KNN + tid] = s_out[tid];
}

// ---------------- K tile kernel: 128x128 tiles, 8x8 register blocking ----
// Split 4+4 tile mapping -> conflict-free LDS.128; __expf epilogue.
__global__ __launch_bounds__(256, 2)
void kmat_kernel(const float* __restrict__ pc0, const float* __restrict__ pc1,
                 const float* __restrict__ epsilon)
{
    extern __shared__ float sm[];
    float* As      = sm;               // 64*132 = 8448
    float* Bs      = sm + 8448;        // 8448
    float* P0      = sm + 16896;       // 3*128
    float* P1      = sm + 17280;       // 3*128
    float* N0s     = sm + 17664;       // 128
    float* N1s     = sm + 17792;       // 128
    float* colpart = sm + 17920;       // 128

    int bz = blockIdx.z;
    int row0 = blockIdx.y*128, col0 = blockIdx.x*128;
    int tid = threadIdx.x;

    {   // load feature tiles, transpose into k-major smem (2 threads/row)
        int r = tid >> 1, q = tid & 1;
        const float* a = g_f0n + (size_t)(bz*NNPTS + row0 + r)*CF + q*32;
        const float* b = g_f1n + (size_t)(bz*NNPTS + col0 + r)*CF + q*32;
        #pragma unroll
        for (int i = 0; i < 8; i++) {
            float4 va = *(const float4*)(a + 4*i);
            float4 vb = *(const float4*)(b + 4*i);
            int k = q*32 + 4*i;
            As[(k+0)*132 + r] = va.x; As[(k+1)*132 + r] = va.y;
            As[(k+2)*132 + r] = va.z; As[(k+3)*132 + r] = va.w;
            Bs[(k+0)*132 + r] = vb.x; Bs[(k+1)*132 + r] = vb.y;
            Bs[(k+2)*132 + r] = vb.z; Bs[(k+3)*132 + r] = vb.w;
        }
    }
    if (tid < 128) {
        int r = tid;
        #pragma unroll
        for (int d = 0; d < 3; d++) P0[d*128 + r] = pc0[(bz*NNPTS+row0+r)*3 + d];
        N0s[r] = g_n0[bz*NNPTS + row0 + r];
        colpart[r] = 0.f;
    } else {
        int r = tid - 128;
        #pragma unroll
        for (int d = 0; d < 3; d++) P1[d*128 + r] = pc1[(bz*NNPTS+col0+r)*3 + d];
        N1s[r] = g_n1[bz*NNPTS + col0 + r];
    }
    __syncthreads();

    int rb = (tid >> 4)*4, cb = (tid & 15)*4;
    float acc[8][8];
    #pragma unroll
    for (int i = 0; i < 8; i++)
        #pragma unroll
        for (int j = 0; j < 8; j++) acc[i][j] = 0.f;

    #pragma unroll 4
    for (int k = 0; k < 64; k++) {
        float4 a0 = *(const float4*)&As[k*132 + rb];
        float4 a1 = *(const float4*)&As[k*132 + rb + 64];
        float4 b0 = *(const float4*)&Bs[k*132 + cb];
        float4 b1 = *(const float4*)&Bs[k*132 + cb + 64];
        float ar[8] = {a0.x,a0.y,a0.z,a0.w,a1.x,a1.y,a1.z,a1.w};
        float br[8] = {b0.x,b0.y,b0.z,b0.w,b1.x,b1.y,b1.z,b1.w};
        #pragma unroll
        for (int i = 0; i < 8; i++)
            #pragma unroll
            for (int j = 0; j < 8; j++)
                acc[i][j] = fmaf(ar[i], br[j], acc[i][j]);
    }

    float p1x[8], p1y[8], p1z[8], n1v[8];
    #pragma unroll
    for (int j = 0; j < 8; j++) {
        int cj = cb + ((j < 4) ? j : 60 + j);     // j>=4 -> cb+64+(j-4)
        p1x[j] = P1[cj]; p1y[j] = P1[128+cj]; p1z[j] = P1[256+cj];
        n1v[j] = N1s[cj];
    }
    float eps = __expf(epsilon[0]) + 0.025f;
    float inv_eps = 1.0f/eps;
    float cs[8];
    #pragma unroll
    for (int j = 0; j < 8; j++) cs[j] = 0.f;
    #pragma unroll
    for (int i = 0; i < 8; i++) {
        int ri = rb + ((i < 4) ? i : 60 + i);
        float p0x = P0[ri], p0y = P0[128+ri], p0z = P0[256+ri];
        float n0v = N0s[ri];
        float kv[8];
        #pragma unroll
        for (int j = 0; j < 8; j++) {
            float pd  = fmaf(p0x, p1x[j], fmaf(p0y, p1y[j], p0z*p1z[j]));
            float sqd = n0v + n1v[j] - 2.0f*pd;
            float v   = (sqd < 100.0f) ? __expf((acc[i][j] - 1.0f)*inv_eps) : 0.0f;
            kv[j] = v; cs[j] += v;
        }
        size_t base = ((size_t)(bz*NNPTS) + row0 + ri)*NNPTS + col0;
        *(float4*)&g_K[base + cb]      = make_float4(kv[0],kv[1],kv[2],kv[3]);
        *(float4*)&g_K[base + cb + 64] = make_float4(kv[4],kv[5],kv[6],kv[7]);
    }
    #pragma unroll
    for (int j = 0; j < 8; j++) {
        int cj = cb + ((j < 4) ? j : 60 + j);
        atomicAdd(&colpart[cj], cs[j]);
    }
    __syncthreads();
    if (tid < 128) atomicAdd(&g_colsum[bz*NNPTS + col0 + tid], colpart[tid]);
}

// -------- b vector, stored transposed for rowpass ------------------------
__global__ __launch_bounds__(256)
void bvec_kernel(const float* __restrict__ pc1,
                 const float* __restrict__ gamma, const float* __restrict__ epsilon)
{
    int i = blockIdx.x*blockDim.x + threadIdx.x;
    if (i >= NTOT) return;
    float eps = expf(epsilon[0]) + 0.025f;
    float gam = expf(gamma[0]);
    float power = gam/(gam+eps);
    float kta = g_colsum[i] * (1.0f/NNPTS);
    float b = powf((1.0f/NNPTS)/(kta + 1e-8f), power);
    int bz = i / NNPTS, c = i % NNPTS;
    g_w4t[bz*NNPTS + (c & 3)*1024 + (c >> 2)] =
        make_float4(b, b*pc1[i*3+0], b*pc1[i*3+1], b*pc1[i*3+2]);
}

// ---------------- row pass: Kb, K b pc1 -> ot_flow ------------------------
__global__ __launch_bounds__(256)
void rowpass_kernel(const float* __restrict__ pc0,
                    const float* __restrict__ gamma, const float* __restrict__ epsilon)
{
    __shared__ float rbuf[8][4][4];
    int tid = threadIdx.x;
    int r0 = blockIdx.x * 4;
    int bz = r0 / NNPTS;
    const float4* wt = g_w4t + bz*NNPTS;
    int wid = tid >> 5, lane = tid & 31;

    const float4* K0 = (const float4*)(g_K + (size_t)(r0+0)*NNPTS);
    const float4* K1 = (const float4*)(g_K + (size_t)(r0+1)*NNPTS);
    const float4* K2 = (const float4*)(g_K + (size_t)(r0+2)*NNPTS);
    const float4* K3 = (const float4*)(g_K + (size_t)(r0+3)*NNPTS);
    float acc[4][4];
    #pragma unroll
    for (int r = 0; r < 4; r++)
        acc[r][0]=acc[r][1]=acc[r][2]=acc[r][3]=0.f;
    #pragma unroll
    for (int i = 0; i < 4; i++) {
        int f = tid + i*256;
        float4 w0 = __ldg(&wt[f]),      w1 = __ldg(&wt[1024+f]);
        float4 w2 = __ldg(&wt[2048+f]), w3 = __ldg(&wt[3072+f]);
        float4 kr[4] = { K0[f], K1[f], K2[f], K3[f] };
        #pragma unroll
        for (int r = 0; r < 4; r++) {
            float4 k = kr[r];
            acc[r][0] = fmaf(k.x,w0.x, fmaf(k.y,w1.x, fmaf(k.z,w2.x, fmaf(k.w,w3.x, acc[r][0]))));
            acc[r][1] = fmaf(k.x,w0.y, fmaf(k.y,w1.y, fmaf(k.z,w2.y, fmaf(k.w,w3.y, acc[r][1]))));
            acc[r][2] = fmaf(k.x,w0.z, fmaf(k.y,w1.z, fmaf(k.z,w2.z, fmaf(k.w,w3.z, acc[r][2]))));
            acc[r][3] = fmaf(k.x,w0.w, fmaf(k.y,w1.w, fmaf(k.z,w2.w, fmaf(k.w,w3.w, acc[r][3]))));
        }
    }
    #pragma unroll
    for (int r = 0; r < 4; r++) {
        #pragma unroll
        for (int o = 16; o > 0; o >>= 1) {
            acc[r][0] += __shfl_xor_sync(0xffffffffu, acc[r][0], o);
            acc[r][1] += __shfl_xor_sync(0xffffffffu, acc[r][1], o);
            acc[r][2] += __shfl_xor_sync(0xffffffffu, acc[r][2], o);
            acc[r][3] += __shfl_xor_sync(0xffffffffu, acc[r][3], o);
        }
        if (lane == 0) {
            rbuf[wid][r][0]=acc[r][0]; rbuf[wid][r][1]=acc[r][1];
            rbuf[wid][r][2]=acc[r][2]; rbuf[wid][r][3]=acc[r][3];
        }
    }
    __syncthreads();
    if (tid < 4) {
        int r = tid;
        float Kb=0.f,Sx=0.f,Sy=0.f,Sz=0.f;
        #pragma unroll
        for (int w = 0; w < 8; w++) {
            Kb += rbuf[w][r][0]; Sx += rbuf[w][r][1];
            Sy += rbuf[w][r][2]; Sz += rbuf[w][r][3];
        }
        float eps = expf(epsilon[0]) + 0.025f;
        float gam = expf(gamma[0]);
        float power = gam/(gam+eps);
        float a  = powf((1.0f/NNPTS)/(Kb + 1e-8f), power);
        float rs = a*Kb;
        float inv = 1.0f/(rs + 1e-8f);
        int row = r0 + r;
        g_otflow[row*3+0] = a*Sx*inv - pc0[row*3+0];
        g_otflow[row*3+1] = a*Sy*inv - pc0[row*3+1];
        g_otflow[row*3+2] = a*Sz*inv - pc0[row*3+2];
    }
}

// ---------------- conv1: edge conv (6->32->32->32) + y2 epilogue ---------
__global__ __launch_bounds__(256)
void conv1_kernel(const float* __restrict__ pc0,
                  const float* __restrict__ W1, const float* __restrict__ B1,
                  const float* __restrict__ B2, const float* __restrict__ B3)
{
    __shared__ __align__(16) float in_s[8][KNN][8];
    __shared__ __align__(16) float h[8][32];
    __shared__ __align__(16) float h2[8][32];
    __shared__ int   nb_s[8][KNN];

    int tid = threadIdx.x;
    int g = tid >> 5, c = tid & 31;
    int node = blockIdx.x*8 + g;
    int b = node / NNPTS;

    nb_s[g][c] = g_idx[node*KNN + c];
    __syncthreads();

    for (int e = c; e < KNN*6; e += 32) {
        int j = e / 6, k = e % 6;
        int nb = nb_s[g][j];
        float v;
        if (k < 3) v = g_otflow[(b*NNPTS + nb)*3 + k];
        else       v = pc0[(b*NNPTS + nb)*3 + (k-3)] - pc0[node*3 + (k-3)];
        in_s[g][j][k] = v;
    }
    __syncthreads();

    float acc[KNN];
    float bias1 = B1[c];
    #pragma unroll
    for (int j = 0; j < KNN; j++) acc[j] = bias1;
    #pragma unroll
    for (int k = 0; k < 6; k++) {
        float w = W1[k*32 + c];
        #pragma unroll
        for (int j = 0; j < KNN; j++) acc[j] = fmaf(in_s[g][j][k], w, acc[j]);
    }
    float mx = -3.4e38f;
    #pragma unroll
    for (int j = 0; j < KNN; j++) mx = fmaxf(mx, lrelu(acc[j]));
    h[g][c] = mx;
    __syncthreads();

    {
        const float4* w4 = (const float4*)(g_t_w12 + c*32);
        const float4* hv = (const float4*)h[g];
        float a2 = B2[c];
        #pragma unroll
        for (int k4 = 0; k4 < 8; k4++) {
            float4 w = w4[k4], x = hv[k4];
            a2 = fmaf(w.x,x.x, fmaf(w.y,x.y, fmaf(w.z,x.z, fmaf(w.w,x.w, a2))));
        }
        h2[g][c] = lrelu(a2);
    }
    __syncthreads();

    {
        const float4* w4 = (const float4*)(g_t_w13 + c*32);
        const float4* hv = (const float4*)h2[g];
        float a3 = B3[c];
        #pragma unroll
        for (int k4 = 0; k4 < 8; k4++) {
            float4 w = w4[k4], x = hv[k4];
            a3 = fmaf(w.x,x.x, fmaf(w.y,x.y, fmaf(w.z,x.z, fmaf(w.w,x.w, a3))));
        }
        h[g][c] = lrelu(a3);
    }
    __syncthreads();

    // y2 epilogue: y2 = x1 @ W2a (32 -> 64), 2 outputs per thread
    #pragma unroll
    for (int t = 0; t < 2; t++) {
        int cc = c + t*32;
        const float4* w4 = (const float4*)(g_t_w2a + cc*32);
        const float4* hv = (const float4*)h[g];
        float y = 0.f;
        #pragma unroll
        for (int k4 = 0; k4 < 8; k4++) {
            float4 w = w4[k4], x = hv[k4];
            y = fmaf(w.x,x.x, fmaf(w.y,x.y, fmaf(w.z,x.z, fmaf(w.w,x.w, y))));
        }
        g_y2[(size_t)node*64 + cc] = y;
    }
}

// ---------------- conv2: gather y2 + edge (3ch) -> 64, dense x2, y3 epi --
__global__ __launch_bounds__(256)
void conv2_kernel(const float* __restrict__ pc0,
                  const float* __restrict__ W1, const float* __restrict__ B1, // w2_1, b2_1
                  const float* __restrict__ B2, const float* __restrict__ B3)
{
    __shared__ int    nb_s[4][KNN];
    __shared__ float4 es[4][KNN];
    __shared__ __align__(16) float h[4][64];
    __shared__ __align__(16) float h2[4][64];

    int tid = threadIdx.x;
    int g = tid >> 6, c = tid & 63;
    int node = blockIdx.x*4 + g;
    int b = node / NNPTS;

    if (c < KNN) {
        int nb = g_idx[node*KNN + c];
        nb_s[g][c] = nb;
        es[g][c] = make_float4(pc0[(b*NNPTS+nb)*3+0] - pc0[node*3+0],
                               pc0[(b*NNPTS+nb)*3+1] - pc0[node*3+1],
                               pc0[(b*NNPTS+nb)*3+2] - pc0[node*3+2], 0.f);
    }
    __syncthreads();

    const float* yb = g_y2 + (size_t)b*NNPTS*64;
    float yv[KNN];
    #pragma unroll
    for (int j = 0; j < KNN; j++) yv[j] = yb[nb_s[g][j]*64 + c];

    float wb0 = W1[32*64 + c], wb1 = W1[33*64 + c], wb2 = W1[34*64 + c];
    float bias = B1[c];
    float mx = -3.4e38f;
    #pragma unroll
    for (int j = 0; j < KNN; j++) {
        float4 e = es[g][j];
        float a = yv[j] + fmaf(e.x, wb0, fmaf(e.y, wb1, fmaf(e.z, wb2, bias)));
        mx = fmaxf(mx, lrelu(a));
    }
    h[g][c] = mx;
    __syncthreads();

    {
        const float4* w4 = (const float4*)(g_t_w22 + c*64);
        const float4* hv = (const float4*)h[g];
        float a2 = B2[c];
        #pragma unroll
        for (int k4 = 0; k4 < 16; k4++) {
            float4 w = w4[k4], x = hv[k4];
            a2 = fmaf(w.x,x.x, fmaf(w.y,x.y, fmaf(w.z,x.z, fmaf(w.w,x.w, a2))));
        }
        h2[g][c] = lrelu(a2);
    }
    __syncthreads();

    {
        const float4* w4 = (const float4*)(g_t_w23 + c*64);
        const float4* hv = (const float4*)h2[g];
        float a3 = B3[c];
        #pragma unroll
        for (int k4 = 0; k4 < 16; k4++) {
            float4 w = w4[k4], x = hv[k4];
            a3 = fmaf(w.x,x.x, fmaf(w.y,x.y, fmaf(w.z,x.z, fmaf(w.w,x.w, a3))));
        }
        h[g][c] = lrelu(a3);
    }
    __syncthreads();

    // y3 epilogue: y3 = x2 @ W3a (64 -> 128), 2 outputs per thread
    #pragma unroll
    for (int t = 0; t < 2; t++) {
        int cc = c + t*64;
        const float4* w4 = (const float4*)(g_t_w3a + cc*64);
        const float4* hv = (const float4*)h[g];
        float y = 0.f;
        #pragma unroll
        for (int k4 = 0; k4 < 16; k4++) {
            float4 w = w4[k4], x = hv[k4];
            y = fmaf(w.x,x.x, fmaf(w.y,x.y, fmaf(w.z,x.z, fmaf(w.w,x.w, y))));
        }
        g_y3[(size_t)node*128 + cc] = y;
    }
}

// ---------------- conv3: gather y3 + edge -> 128, dense, fc, residual ----
__global__ __launch_bounds__(256)
void conv3_kernel(const float* __restrict__ pc0,
                  const float* __restrict__ W1, const float* __restrict__ B1, // w3_1, b3_1
                  const float* __restrict__ B2, const float* __restrict__ B3,
                  const float* __restrict__ Wfc, const float* __restrict__ Bfc,
                  float* __restrict__ dout)
{
    __shared__ int    nb_s[2][KNN];
    __shared__ float4 es[2][KNN];
    __shared__ __align__(16) float h[2][128];
    __shared__ __align__(16) float h2[2][128];

    int tid = threadIdx.x;
    int g = tid >> 7, c = tid & 127;
    int node = blockIdx.x*2 + g;
    int b = node / NNPTS;

    if (c < KNN) {
        int nb = g_idx[node*KNN + c];
        nb_s[g][c] = nb;
        es[g][c] = make_float4(pc0[(b*NNPTS+nb)*3+0] - pc0[node*3+0],
                               pc0[(b*NNPTS+nb)*3+1] - pc0[node*3+1],
                               pc0[(b*NNPTS+nb)*3+2] - pc0[node*3+2], 0.f);
    }
    __syncthreads();

    const float* yb = g_y3 + (size_t)b*NNPTS*128;
    float yv[KNN];
    #pragma unroll
    for (int j = 0; j < KNN; j++) yv[j] = yb[nb_s[g][j]*128 + c];

    float wb0 = W1[64*128 + c], wb1 = W1[65*128 + c], wb2 = W1[66*128 + c];
    float bias = B1[c];
    float mx = -3.4e38f;
    #pragma unroll
    for (int j = 0; j < KNN; j++) {
        float4 e = es[g][j];
        float a = yv[j] + fmaf(e.x, wb0, fmaf(e.y, wb1, fmaf(e.z, wb2, bias)));
        mx = fmaxf(mx, lrelu(a));
    }
    h[g][c] = mx;
    __syncthreads();

    {
        const float4* w4 = (const float4*)(g_t_w32 + c*128);
        const float4* hv = (const float4*)h[g];
        float a2 = B2[c];
        #pragma unroll
        for (int k4 = 0; k4 < 32; k4++) {
            float4 w = w4[k4], x = hv[k4];
            a2 = fmaf(w.x,x.x, fmaf(w.y,x.y, fmaf(w.z,x.z, fmaf(w.w,x.w, a2))));
        }
        h2[g][c] = lrelu(a2);
    }
    __syncthreads();

    {
        const float4* w4 = (const float4*)(g_t_w33 + c*128);
        const float4* hv = (const float4*)h2[g];
        float a3 = B3[c];
        #pragma unroll
        for (int k4 = 0; k4 < 32; k4++) {
            float4 w = w4[k4], x = hv[k4];
            a3 = fmaf(w.x,x.x, fmaf(w.y,x.y, fmaf(w.z,x.z, fmaf(w.w,x.w, a3))));
        }
        h[g][c] = lrelu(a3);
    }
    __syncthreads();

    if (c < 3) {
        float o = Bfc[c];
        for (int k = 0; k < 128; k++) o = fmaf(h[g][k], Wfc[k*3 + c], o);
        dout[node*3 + c] = g_otflow[node*3 + c] + o;
    }
}

// ---------------- launch --------------------------------------------------
extern "C" void kernel_launch(void* const* d_in, const int* in_sizes, int n_in,
                              void* d_out, int out_size)
{
    const float* pc0   = (const float*)d_in[0];
    const float* pc1   = (const float*)d_in[1];
    const float* f0    = (const float*)d_in[2];
    const float* f1    = (const float*)d_in[3];
    const float* gamma = (const float*)d_in[4];
    const float* eps   = (const float*)d_in[5];
    const float* w1_1=(const float*)d_in[6],  *b1_1=(const float*)d_in[7];
    const float* w1_2=(const float*)d_in[8],  *b1_2=(const float*)d_in[9];
    const float* w1_3=(const float*)d_in[10], *b1_3=(const float*)d_in[11];
    const float* w2_1=(const float*)d_in[12], *b2_1=(const float*)d_in[13];
    const float* w2_2=(const float*)d_in[14], *b2_2=(const float*)d_in[15];
    const float* w2_3=(const float*)d_in[16], *b2_3=(const float*)d_in[17];
    const float* w3_1=(const float*)d_in[18], *b3_1=(const float*)d_in[19];
    const float* w3_2=(const float*)d_in[20], *b3_2=(const float*)d_in[21];
    const float* w3_3=(const float*)d_in[22], *b3_3=(const float*)d_in[23];
    const float* wfc =(const float*)d_in[24], *bfc =(const float*)d_in[25];
    float* out = (float*)d_out;

    cudaFuncSetAttribute(kmat_kernel, cudaFuncAttributeMaxDynamicSharedMemorySize, 73728);

    prep_norm_kernel<<<(2*NTOT + 255)/256, 256>>>(pc0, pc1);      // 1
    knn_kernel<<<NTOT, 256>>>();                                   // 2
    prep_feat_kernel<<<2048, 256>>>(f0, f1);                       // 3
    kmat_kernel<<<dim3(NNPTS/128, NNPTS/128, BB), 256, 72192>>>(pc0, pc1, eps); // 4 = ncu slot
    bvec_kernel<<<(NTOT + 255)/256, 256>>>(pc1, gamma, eps);
    wtrans_kernel<<<124, 256>>>(w1_2, w1_3, w2_2, w2_3, w3_2, w3_3, w2_1, w3_1);
    rowpass_kernel<<<NTOT/4, 256>>>(pc0, gamma, eps);
    conv1_kernel<<<NTOT/8, 256>>>(pc0, w1_1, b1_1, b1_2, b1_3);
    conv2_kernel<<<NTOT/4, 256>>>(pc0, w2_1, b2_1, b2_2, b2_3);
    conv3_kernel<<<NTOT/2, 256>>>(pc0, w3_1, b3_1, b3_2, b3_3, wfc, bfc, out);
}

// round 11
// speedup vs baseline: 1.8363x; 1.8363x over previous
#include <cuda_runtime.h>
#include <math.h>
#include <stdint.h>

#define BB 2
#define NNPTS 4096
#define CF 64
#define KNN 32
#define NTOT (BB*NNPTS)

// ---------------- scratch (static __device__, no allocs) ----------------
__device__ float  g_K[(size_t)BB*NNPTS*NNPTS];   // 128 MB transport kernel
__device__ float  g_f0n[NTOT*CF];
__device__ float  g_f1n[NTOT*CF];
__device__ float  g_n0[NTOT];
__device__ float  g_n1[NTOT];
__device__ float4 g_pts0[NTOT];                  // packed (x,y,z,|p|^2) of pc0
__device__ float  g_colsum[NTOT];
__device__ float4 g_w4t[NTOT];                   // transposed (b, b*x, b*y, b*z)
__device__ float  g_otflow[NTOT*3];
__device__ int    g_idx[NTOT*KNN];
__device__ float  g_y2[NTOT*64];                 // x1 @ W2a (pre-gather transform)
__device__ float  g_y3[NTOT*128];                // x2 @ W3a

__device__ __forceinline__ float lrelu(float x){ return (x > 0.f) ? x : 0.1f*x; }

// ---------------- prep part 1: point norms + packed pts + colsum zero ----
__global__ __launch_bounds__(256)
void prep_norm_kernel(const float* __restrict__ pc0, const float* __restrict__ pc1)
{
    int i = blockIdx.x*blockDim.x + threadIdx.x;
    if (i >= 2*NTOT) return;
    int which = i / NTOT, row = i % NTOT;
    const float* pc = which ? pc1 : pc0;
    float x = pc[row*3+0], y = pc[row*3+1], z = pc[row*3+2];
    float n2 = x*x + y*y + z*z;
    if (which) g_n1[row] = n2;
    else {
        g_n0[row] = n2; g_colsum[row] = 0.f;
        g_pts0[row] = make_float4(x, y, z, n2);
    }
}

// ---------------- prep part 2: feature normalize -------------------------
__global__ __launch_bounds__(256)
void prep_feat_kernel(const float* __restrict__ f0, const float* __restrict__ f1)
{
    int w    = (blockIdx.x*blockDim.x + threadIdx.x) >> 5;
    int lane = threadIdx.x & 31;
    if (w >= 2*NTOT) return;
    int which = w / NTOT;
    int row   = w % NTOT;
    const float* f = which ? f1 : f0;
    float v0 = f[row*CF + lane];
    float v1 = f[row*CF + 32 + lane];
    float ss = v0*v0 + v1*v1;
    #pragma unroll
    for (int o = 16; o > 0; o >>= 1) ss += __shfl_xor_sync(0xffffffffu, ss, o);
    float inv = rsqrtf(ss + 1e-8f);
    float* out = which ? g_f1n : g_f0n;
    out[row*CF + lane]      = v0*inv;
    out[row*CF + 32 + lane] = v1*inv;
}

// ---------------- KNN: radix-select 32 smallest sqdists per row ----------
__global__ __launch_bounds__(256)
void knn_kernel()
{
    int n = blockIdx.x; int b = n / NNPTS;
    const float4* pts = g_pts0 + b*NNPTS;
    int tid = threadIdx.x;
    int lane = tid & 31;
    float4 q = g_pts0[n];
    unsigned key[16];
    #pragma unroll
    for (int i = 0; i < 16; i++) {
        float4 p = pts[tid + i*256];
        float dot = fmaf(p.x, q.x, fmaf(p.y, q.y, p.z*q.z));
        float d = q.w + p.w - 2.0f*dot;
        unsigned u = __float_as_uint(d);
        u = (u & 0x80000000u) ? ~u : (u | 0x80000000u);
        key[i] = u;
    }
    __shared__ int hist[256];
    __shared__ unsigned s_prefix;
    __shared__ int s_krem, s_cl, s_ct;
    __shared__ int s_out[KNN];
    __shared__ int s_tie[64];
    if (tid == 0) { s_prefix = 0u; s_krem = KNN; s_cl = 0; s_ct = 0; }
    for (int r = 0; r < 4; r++) {
        int shift = 24 - 8*r;
        hist[tid] = 0;
        __syncthreads();
        unsigned pref = s_prefix;
        unsigned msk  = (r == 0) ? 0u : (0xFFFFFFFFu << (32 - 8*r));
        #pragma unroll
        for (int i = 0; i < 16; i++)
            if ((key[i] & msk) == (pref & msk))
                atomicAdd(&hist[(key[i] >> shift) & 255], 1);
        __syncthreads();
        if (tid < 32) {                    // warp-0 parallel scan of 256 bins
            int krem = s_krem;
            int loc[8]; int tot = 0;
            #pragma unroll
            for (int j = 0; j < 8; j++) { loc[j] = hist[tid*8 + j]; tot += loc[j]; }
            int incl = tot;
            #pragma unroll
            for (int o = 1; o < 32; o <<= 1) {
                int x = __shfl_up_sync(0xffffffffu, incl, o);
                if (lane >= o) incl += x;
            }
            int excl = incl - tot;
            if (excl < krem && krem <= incl) {
                int rem = krem - excl;
                int d = 0;
                #pragma unroll
                for (int j = 0; j < 7; j++) if (rem > loc[d]) { rem -= loc[d]; d++; }
                s_prefix = pref | ((unsigned)(tid*8 + d) << shift);
                s_krem = rem;
            }
        }
        __syncthreads();
    }
    unsigned pivot = s_prefix;
    #pragma unroll
    for (int i = 0; i < 16; i++) {
        unsigned u = key[i];
        if (u < pivot)       { int p = atomicAdd(&s_cl, 1); s_out[p] = tid + i*256; }
        else if (u == pivot) { int t = atomicAdd(&s_ct, 1); if (t < 64) s_tie[t] = tid + i*256; }
    }
    __syncthreads();
    if (tid == 0) {
        int cl = s_cl;
        int nt = (s_ct < 64) ? s_ct : 64;
        int need = KNN - cl;                 // ties filled by lowest index (jax tie-break)
        for (int s = 0; s < need; s++) {
            int best = 0x7FFFFFFF, bi = 0;
            for (int t = 0; t < nt; t++) if (s_tie[t] < best) { best = s_tie[t]; bi = t; }
            s_tie[bi] = 0x7FFFFFFF;
            s_out[cl + s] = best;
        }
    }
    __syncthreads();
    if (tid < KNN) g_idx[n*KNN + tid] = s_out[tid];
}

// ---------------- K tile kernel: 128x128 tiles, 8x8 register blocking ----
// Split 4+4 tile mapping -> conflict-free LDS.128; __expf epilogue.
__global__ __launch_bounds__(256, 2)
void kmat_kernel(const float* __restrict__ pc0, const float* __restrict__ pc1,
                 const float* __restrict__ epsilon)
{
    extern __shared__ float sm[];
    float* As      = sm;               // 64*132 = 8448
    float* Bs      = sm + 8448;        // 8448
    float* P0      = sm + 16896;       // 3*128
    float* P1      = sm + 17280;       // 3*128
    float* N0s     = sm + 17664;       // 128
    float* N1s     = sm + 17792;       // 128
    float* colpart = sm + 17920;       // 128

    int bz = blockIdx.z;
    int row0 = blockIdx.y*128, col0 = blockIdx.x*128;
    int tid = threadIdx.x;

    {   // load feature tiles, transpose into k-major smem (2 threads/row)
        int r = tid >> 1, q = tid & 1;
        const float* a = g_f0n + (size_t)(bz*NNPTS + row0 + r)*CF + q*32;
        const float* b = g_f1n + (size_t)(bz*NNPTS + col0 + r)*CF + q*32;
        #pragma unroll
        for (int i = 0; i < 8; i++) {
            float4 va = *(const float4*)(a + 4*i);
            float4 vb = *(const float4*)(b + 4*i);
            int k = q*32 + 4*i;
            As[(k+0)*132 + r] = va.x; As[(k+1)*132 + r] = va.y;
            As[(k+2)*132 + r] = va.z; As[(k+3)*132 + r] = va.w;
            Bs[(k+0)*132 + r] = vb.x; Bs[(k+1)*132 + r] = vb.y;
            Bs[(k+2)*132 + r] = vb.z; Bs[(k+3)*132 + r] = vb.w;
        }
    }
    if (tid < 128) {
        int r = tid;
        #pragma unroll
        for (int d = 0; d < 3; d++) P0[d*128 + r] = pc0[(bz*NNPTS+row0+r)*3 + d];
        N0s[r] = g_n0[bz*NNPTS + row0 + r];
        colpart[r] = 0.f;
    } else {
        int r = tid - 128;
        #pragma unroll
        for (int d = 0; d < 3; d++) P1[d*128 + r] = pc1[(bz*NNPTS+col0+r)*3 + d];
        N1s[r] = g_n1[bz*NNPTS + col0 + r];
    }
    __syncthreads();

    int rb = (tid >> 4)*4, cb = (tid & 15)*4;
    float acc[8][8];
    #pragma unroll
    for (int i = 0; i < 8; i++)
        #pragma unroll
        for (int j = 0; j < 8; j++) acc[i][j] = 0.f;

    #pragma unroll 4
    for (int k = 0; k < 64; k++) {
        float4 a0 = *(const float4*)&As[k*132 + rb];
        float4 a1 = *(const float4*)&As[k*132 + rb + 64];
        float4 b0 = *(const float4*)&Bs[k*132 + cb];
        float4 b1 = *(const float4*)&Bs[k*132 + cb + 64];
        float ar[8] = {a0.x,a0.y,a0.z,a0.w,a1.x,a1.y,a1.z,a1.w};
        float br[8] = {b0.x,b0.y,b0.z,b0.w,b1.x,b1.y,b1.z,b1.w};
        #pragma unroll
        for (int i = 0; i < 8; i++)
            #pragma unroll
            for (int j = 0; j < 8; j++)
                acc[i][j] = fmaf(ar[i], br[j], acc[i][j]);
    }

    float p1x[8], p1y[8], p1z[8], n1v[8];
    #pragma unroll
    for (int j = 0; j < 8; j++) {
        int cj = cb + ((j < 4) ? j : 60 + j);     // j>=4 -> cb+64+(j-4)
        p1x[j] = P1[cj]; p1y[j] = P1[128+cj]; p1z[j] = P1[256+cj];
        n1v[j] = N1s[cj];
    }
    float eps = __expf(epsilon[0]) + 0.025f;
    float inv_eps = 1.0f/eps;
    float cs[8];
    #pragma unroll
    for (int j = 0; j < 8; j++) cs[j] = 0.f;
    #pragma unroll
    for (int i = 0; i < 8; i++) {
        int ri = rb + ((i < 4) ? i : 60 + i);
        float p0x = P0[ri], p0y = P0[128+ri], p0z = P0[256+ri];
        float n0v = N0s[ri];
        float kv[8];
        #pragma unroll
        for (int j = 0; j < 8; j++) {
            float pd  = fmaf(p0x, p1x[j], fmaf(p0y, p1y[j], p0z*p1z[j]));
            float sqd = n0v + n1v[j] - 2.0f*pd;
            float v   = (sqd < 100.0f) ? __expf((acc[i][j] - 1.0f)*inv_eps) : 0.0f;
            kv[j] = v; cs[j] += v;
        }
        size_t base = ((size_t)(bz*NNPTS) + row0 + ri)*NNPTS + col0;
        *(float4*)&g_K[base + cb]      = make_float4(kv[0],kv[1],kv[2],kv[3]);
        *(float4*)&g_K[base + cb + 64] = make_float4(kv[4],kv[5],kv[6],kv[7]);
    }
    #pragma unroll
    for (int j = 0; j < 8; j++) {
        int cj = cb + ((j < 4) ? j : 60 + j);
        atomicAdd(&colpart[cj], cs[j]);
    }
    __syncthreads();
    if (tid < 128) atomicAdd(&g_colsum[bz*NNPTS + col0 + tid], colpart[tid]);
}

// -------- b vector, stored transposed for rowpass ------------------------
__global__ __launch_bounds__(256)
void bvec_kernel(const float* __restrict__ pc1,
                 const float* __restrict__ gamma, const float* __restrict__ epsilon)
{
    int i = blockIdx.x*blockDim.x + threadIdx.x;
    if (i >= NTOT) return;
    float eps = expf(epsilon[0]) + 0.025f;
    float gam = expf(gamma[0]);
    float power = gam/(gam+eps);
    float kta = g_colsum[i] * (1.0f/NNPTS);
    float b = powf((1.0f/NNPTS)/(kta + 1e-8f), power);
    int bz = i / NNPTS, c = i % NNPTS;
    g_w4t[bz*NNPTS + (c & 3)*1024 + (c >> 2)] =
        make_float4(b, b*pc1[i*3+0], b*pc1[i*3+1], b*pc1[i*3+2]);
}

// ---------------- row pass: Kb, K b pc1 -> ot_flow ------------------------
__global__ __launch_bounds__(256)
void rowpass_kernel(const float* __restrict__ pc0,
                    const float* __restrict__ gamma, const float* __restrict__ epsilon)
{
    __shared__ float rbuf[8][4][4];
    int tid = threadIdx.x;
    int r0 = blockIdx.x * 4;
    int bz = r0 / NNPTS;
    const float4* wt = g_w4t + bz*NNPTS;
    int wid = tid >> 5, lane = tid & 31;

    const float4* K0 = (const float4*)(g_K + (size_t)(r0+0)*NNPTS);
    const float4* K1 = (const float4*)(g_K + (size_t)(r0+1)*NNPTS);
    const float4* K2 = (const float4*)(g_K + (size_t)(r0+2)*NNPTS);
    const float4* K3 = (const float4*)(g_K + (size_t)(r0+3)*NNPTS);
    float acc[4][4];
    #pragma unroll
    for (int r = 0; r < 4; r++)
        acc[r][0]=acc[r][1]=acc[r][2]=acc[r][3]=0.f;
    #pragma unroll
    for (int i = 0; i < 4; i++) {
        int f = tid + i*256;
        float4 w0 = __ldg(&wt[f]),      w1 = __ldg(&wt[1024+f]);
        float4 w2 = __ldg(&wt[2048+f]), w3 = __ldg(&wt[3072+f]);
        float4 kr[4] = { K0[f], K1[f], K2[f], K3[f] };
        #pragma unroll
        for (int r = 0; r < 4; r++) {
            float4 k = kr[r];
            acc[r][0] = fmaf(k.x,w0.x, fmaf(k.y,w1.x, fmaf(k.z,w2.x, fmaf(k.w,w3.x, acc[r][0]))));
            acc[r][1] = fmaf(k.x,w0.y, fmaf(k.y,w1.y, fmaf(k.z,w2.y, fmaf(k.w,w3.y, acc[r][1]))));
            acc[r][2] = fmaf(k.x,w0.z, fmaf(k.y,w1.z, fmaf(k.z,w2.z, fmaf(k.w,w3.z, acc[r][2]))));
            acc[r][3] = fmaf(k.x,w0.w, fmaf(k.y,w1.w, fmaf(k.z,w2.w, fmaf(k.w,w3.w, acc[r][3]))));
        }
    }
    #pragma unroll
    for (int r = 0; r < 4; r++) {
        #pragma unroll
        for (int o = 16; o > 0; o >>= 1) {
            acc[r][0] += __shfl_xor_sync(0xffffffffu, acc[r][0], o);
            acc[r][1] += __shfl_xor_sync(0xffffffffu, acc[r][1], o);
            acc[r][2] += __shfl_xor_sync(0xffffffffu, acc[r][2], o);
            acc[r][3] += __shfl_xor_sync(0xffffffffu, acc[r][3], o);
        }
        if (lane == 0) {
            rbuf[wid][r][0]=acc[r][0]; rbuf[wid][r][1]=acc[r][1];
            rbuf[wid][r][2]=acc[r][2]; rbuf[wid][r][3]=acc[r][3];
        }
    }
    __syncthreads();
    if (tid < 4) {
        int r = tid;
        float Kb=0.f,Sx=0.f,Sy=0.f,Sz=0.f;
        #pragma unroll
        for (int w = 0; w < 8; w++) {
            Kb += rbuf[w][r][0]; Sx += rbuf[w][r][1];
            Sy += rbuf[w][r][2]; Sz += rbuf[w][r][3];
        }
        float eps = expf(epsilon[0]) + 0.025f;
        float gam = expf(gamma[0]);
        float power = gam/(gam+eps);
        float a  = powf((1.0f/NNPTS)/(Kb + 1e-8f), power);
        float rs = a*Kb;
        float inv = 1.0f/(rs + 1e-8f);
        int row = r0 + r;
        g_otflow[row*3+0] = a*Sx*inv - pc0[row*3+0];
        g_otflow[row*3+1] = a*Sy*inv - pc0[row*3+1];
        g_otflow[row*3+2] = a*Sz*inv - pc0[row*3+2];
    }
}

// ---------------- conv1: edge conv (6->32->32->32) + y2 epilogue ---------
__global__ __launch_bounds__(256)
void conv1_kernel(const float* __restrict__ pc0,
                  const float* __restrict__ W1, const float* __restrict__ B1,
                  const float* __restrict__ W2, const float* __restrict__ B2,
                  const float* __restrict__ W3, const float* __restrict__ B3,
                  const float* __restrict__ W2a)   // w2_1 (35x64), rows 0..31
{
    __shared__ __align__(16) float in_s[8][KNN][8];
    __shared__ float h[8][32];
    __shared__ float h2[8][32];
    __shared__ int   nb_s[8][KNN];

    int tid = threadIdx.x;
    int g = tid >> 5, c = tid & 31;
    int node = blockIdx.x*8 + g;
    int b = node / NNPTS;

    nb_s[g][c] = g_idx[node*KNN + c];
    __syncthreads();

    for (int e = c; e < KNN*6; e += 32) {
        int j = e / 6, k = e % 6;
        int nb = nb_s[g][j];
        float v;
        if (k < 3) v = g_otflow[(b*NNPTS + nb)*3 + k];
        else       v = pc0[(b*NNPTS + nb)*3 + (k-3)] - pc0[node*3 + (k-3)];
        in_s[g][j][k] = v;
    }
    __syncthreads();

    float acc[KNN];
    float bias1 = B1[c];
    #pragma unroll
    for (int j = 0; j < KNN; j++) acc[j] = bias1;
    #pragma unroll
    for (int k = 0; k < 6; k++) {
        float w = W1[k*32 + c];
        #pragma unroll
        for (int j = 0; j < KNN; j++) acc[j] = fmaf(in_s[g][j][k], w, acc[j]);
    }
    float mx = -3.4e38f;
    #pragma unroll
    for (int j = 0; j < KNN; j++) mx = fmaxf(mx, lrelu(acc[j]));
    h[g][c] = mx;
    __syncthreads();

    float a2 = B2[c];
    for (int k = 0; k < 32; k++) a2 = fmaf(h[g][k], W2[k*32 + c], a2);
    h2[g][c] = lrelu(a2);
    __syncthreads();

    float a3 = B3[c];
    for (int k = 0; k < 32; k++) a3 = fmaf(h2[g][k], W3[k*32 + c], a3);
    h[g][c] = lrelu(a3);
    __syncthreads();

    // y2 epilogue: y2 = x1 @ W2a (32 -> 64), 2 outputs per thread
    #pragma unroll
    for (int t = 0; t < 2; t++) {
        int cc = c + t*32;
        float y = 0.f;
        for (int k = 0; k < 32; k++) y = fmaf(h[g][k], W2a[k*64 + cc], y);
        g_y2[(size_t)node*64 + cc] = y;
    }
}

// ---------------- conv2: gather y2 + edge (3ch) -> 64, dense x2, y3 epi --
__global__ __launch_bounds__(256)
void conv2_kernel(const float* __restrict__ pc0,
                  const float* __restrict__ W1, const float* __restrict__ B1, // w2_1, b2_1
                  const float* __restrict__ W2, const float* __restrict__ B2,
                  const float* __restrict__ W3, const float* __restrict__ B3,
                  const float* __restrict__ W3a)   // w3_1 (67x128), rows 0..63
{
    __shared__ int    nb_s[4][KNN];
    __shared__ float4 es[4][KNN];
    __shared__ float  h[4][64];
    __shared__ float  h2[4][64];

    int tid = threadIdx.x;
    int g = tid >> 6, c = tid & 63;
    int node = blockIdx.x*4 + g;
    int b = node / NNPTS;

    if (c < KNN) {
        int nb = g_idx[node*KNN + c];
        nb_s[g][c] = nb;
        es[g][c] = make_float4(pc0[(b*NNPTS+nb)*3+0] - pc0[node*3+0],
                               pc0[(b*NNPTS+nb)*3+1] - pc0[node*3+1],
                               pc0[(b*NNPTS+nb)*3+2] - pc0[node*3+2], 0.f);
    }
    __syncthreads();

    const float* yb = g_y2 + (size_t)b*NNPTS*64;
    float yv[KNN];
    #pragma unroll
    for (int j = 0; j < KNN; j++) yv[j] = yb[nb_s[g][j]*64 + c];

    float wb0 = W1[32*64 + c], wb1 = W1[33*64 + c], wb2 = W1[34*64 + c];
    float bias = B1[c];
    float mx = -3.4e38f;
    #pragma unroll
    for (int j = 0; j < KNN; j++) {
        float4 e = es[g][j];
        float a = yv[j] + fmaf(e.x, wb0, fmaf(e.y, wb1, fmaf(e.z, wb2, bias)));
        mx = fmaxf(mx, lrelu(a));
    }
    h[g][c] = mx;
    __syncthreads();

    float a2 = B2[c];
    for (int k = 0; k < 64; k++) a2 = fmaf(h[g][k], W2[k*64 + c], a2);
    h2[g][c] = lrelu(a2);
    __syncthreads();

    float a3 = B3[c];
    for (int k = 0; k < 64; k++) a3 = fmaf(h2[g][k], W3[k*64 + c], a3);
    h[g][c] = lrelu(a3);
    __syncthreads();

    // y3 epilogue: y3 = x2 @ W3a (64 -> 128), 2 outputs per thread
    #pragma unroll
    for (int t = 0; t < 2; t++) {
        int cc = c + t*64;
        float y = 0.f;
        for (int k = 0; k < 64; k++) y = fmaf(h[g][k], W3a[k*128 + cc], y);
        g_y3[(size_t)node*128 + cc] = y;
    }
}

// ---------------- conv3: gather y3 + edge -> 128, dense, fc, residual ----
__global__ __launch_bounds__(256)
void conv3_kernel(const float* __restrict__ pc0,
                  const float* __restrict__ W1, const float* __restrict__ B1, // w3_1, b3_1
                  const float* __restrict__ W2, const float* __restrict__ B2,
                  const float* __restrict__ W3, const float* __restrict__ B3,
                  const float* __restrict__ Wfc, const float* __restrict__ Bfc,
                  float* __restrict__ dout)
{
    __shared__ int    nb_s[2][KNN];
    __shared__ float4 es[2][KNN];
    __shared__ float  h[2][128];
    __shared__ float  h2[2][128];

    int tid = threadIdx.x;
    int g = tid >> 7, c = tid & 127;
    int node = blockIdx.x*2 + g;
    int b = node / NNPTS;

    if (c < KNN) {
        int nb = g_idx[node*KNN + c];
        nb_s[g][c] = nb;
        es[g][c] = make_float4(pc0[(b*NNPTS+nb)*3+0] - pc0[node*3+0],
                               pc0[(b*NNPTS+nb)*3+1] - pc0[node*3+1],
                               pc0[(b*NNPTS+nb)*3+2] - pc0[node*3+2], 0.f);
    }
    __syncthreads();

    const float* yb = g_y3 + (size_t)b*NNPTS*128;
    float yv[KNN];
    #pragma unroll
    for (int j = 0; j < KNN; j++) yv[j] = yb[nb_s[g][j]*128 + c];

    float wb0 = W1[64*128 + c], wb1 = W1[65*128 + c], wb2 = W1[66*128 + c];
    float bias = B1[c];
    float mx = -3.4e38f;
    #pragma unroll
    for (int j = 0; j < KNN; j++) {
        float4 e = es[g][j];
        float a = yv[j] + fmaf(e.x, wb0, fmaf(e.y, wb1, fmaf(e.z, wb2, bias)));
        mx = fmaxf(mx, lrelu(a));
    }
    h[g][c] = mx;
    __syncthreads();

    float a2 = B2[c];
    for (int k = 0; k < 128; k++) a2 = fmaf(h[g][k], W2[k*128 + c], a2);
    h2[g][c] = lrelu(a2);
    __syncthreads();

    float a3 = B3[c];
    for (int k = 0; k < 128; k++) a3 = fmaf(h2[g][k], W3[k*128 + c], a3);
    h[g][c] = lrelu(a3);
    __syncthreads();

    if (c < 3) {
        float o = Bfc[c];
        for (int k = 0; k < 128; k++) o = fmaf(h[g][k], Wfc[k*3 + c], o);
        dout[node*3 + c] = g_otflow[node*3 + c] + o;
    }
}

// ---------------- launch --------------------------------------------------
extern "C" void kernel_launch(void* const* d_in, const int* in_sizes, int n_in,
                              void* d_out, int out_size)
{
    const float* pc0   = (const float*)d_in[0];
    const float* pc1   = (const float*)d_in[1];
    const float* f0    = (const float*)d_in[2];
    const float* f1    = (const float*)d_in[3];
    const float* gamma = (const float*)d_in[4];
    const float* eps   = (const float*)d_in[5];
    const float* w1_1=(const float*)d_in[6],  *b1_1=(const float*)d_in[7];
    const float* w1_2=(const float*)d_in[8],  *b1_2=(const float*)d_in[9];
    const float* w1_3=(const float*)d_in[10], *b1_3=(const float*)d_in[11];
    const float* w2_1=(const float*)d_in[12], *b2_1=(const float*)d_in[13];
    const float* w2_2=(const float*)d_in[14], *b2_2=(const float*)d_in[15];
    const float* w2_3=(const float*)d_in[16], *b2_3=(const float*)d_in[17];
    const float* w3_1=(const float*)d_in[18], *b3_1=(const float*)d_in[19];
    const float* w3_2=(const float*)d_in[20], *b3_2=(const float*)d_in[21];
    const float* w3_3=(const float*)d_in[22], *b3_3=(const float*)d_in[23];
    const float* wfc =(const float*)d_in[24], *bfc =(const float*)d_in[25];
    float* out = (float*)d_out;

    cudaFuncSetAttribute(kmat_kernel, cudaFuncAttributeMaxDynamicSharedMemorySize, 73728);

    prep_norm_kernel<<<(2*NTOT + 255)/256, 256>>>(pc0, pc1);      // 1
    knn_kernel<<<NTOT, 256>>>();                                   // 2
    prep_feat_kernel<<<2048, 256>>>(f0, f1);                       // 3
    kmat_kernel<<<dim3(NNPTS/128, NNPTS/128, BB), 256, 72192>>>(pc0, pc1, eps); // 4 = ncu slot
    bvec_kernel<<<(NTOT + 255)/256, 256>>>(pc1, gamma, eps);
    rowpass_kernel<<<NTOT/4, 256>>>(pc0, gamma, eps);
    conv1_kernel<<<NTOT/8, 256>>>(pc0, w1_1,b1_1, w1_2,b1_2, w1_3,b1_3, w2_1);
    conv2_kernel<<<NTOT/4, 256>>>(pc0, w2_1,b2_1, w2_2,b2_2, w2_3,b2_3, w3_1);
    conv3_kernel<<<NTOT/2, 256>>>(pc0, w3_1,b3_1, w3_2,b3_2, w3_3,b3_3, wfc,bfc, out);
}